// round 11
// baseline (speedup 1.0000x reference)
#include <cuda_runtime.h>

#define NTd 4096
#define NROWS 2048
#define NPd 100
#define HPc (1.0f / 99.0f)
#define THREADS 256
#define CHUNK (NTd / THREADS)   // 16
#define WINF 0.26794919243112270f   // 2 - sqrt(3), Thomas coeff limit
// padded chunk layout: chunk c at sF[20*c .. 20*c+15]; 16B-aligned for STS.128
#define IDX2(j) (((j) >> 4) * 20 + ((j) & 15))

__device__ float g_partials[NROWS];
__device__ unsigned int g_count = 0;

// exact Thomas elimination coefficients w_m = 1/(4 - w_{m-1}); w_m == WINF (in fp32) for m >= 6
__constant__ float cW12[12] = {
    0.25f,
    0.26666666666666666f,
    0.26785714285714285f,
    0.26794258373205740f,
    0.26794871794871794f,
    0.26794915836482310f,
    0.26794918998527240f,
    0.26794919225552000f,
    0.26794919241862690f,
    0.26794919243035000f,
    0.26794919243117080f,
    0.26794919243112270f
};

struct SharedBlk {
    float sF[THREADS * 20];     // padded CDF (obs phase), 20KB, float4-aligned
    float sFirst[THREADS];      // first element of each thread's chunk
    float sWarp[8];
    float sTot[1];
    float sQ[NPd];              // quantile function values
    float sR[NPd];              // Thomas rhs
    float sDp[NPd];             // Thomas forward-sweep values
    float sM[NPd];              // spline second derivatives M[0..99]
    float4 coef[NPd];           // packed {a,b,c,d} per segment (99 used)
    int isLast;
};

__device__ __forceinline__ float warp_incl_scan(float v) {
    int lane = threadIdx.x & 31;
    #pragma unroll
    for (int o = 1; o < 32; o <<= 1) {
        float tv = __shfl_up_sync(0xffffffffu, v, o);
        if (lane >= o) v += tv;
    }
    return v;
}

// exclusive scan; also returns the block-wide total (free: sWarp[7] after stage 2)
__device__ __forceinline__ float block_excl_scan_total(float v, SharedBlk* sh, float* total) {
    int tid = threadIdx.x, lane = tid & 31, w = tid >> 5;
    __syncthreads();                 // protect sWarp reuse across calls
    float incl = warp_incl_scan(v);
    if (lane == 31) sh->sWarp[w] = incl;
    __syncthreads();
    if (w == 0) {
        float x = (lane < 8) ? sh->sWarp[lane] : 0.0f;
        float xs = warp_incl_scan(x);
        if (lane < 8) sh->sWarp[lane] = xs;
    }
    __syncthreads();
    float off = (w > 0) ? sh->sWarp[w - 1] : 0.0f;
    *total = sh->sWarp[7];
    return off + incl - v;
}

__device__ __forceinline__ float block_reduce_bcast(float v, SharedBlk* sh) {
    int tid = threadIdx.x, lane = tid & 31, w = tid >> 5;
    __syncthreads();
    #pragma unroll
    for (int o = 16; o > 0; o >>= 1) v += __shfl_down_sync(0xffffffffu, v, o);
    if (lane == 0) sh->sWarp[w] = v;
    __syncthreads();
    if (tid == 0) {
        float s = 0.0f;
        #pragma unroll
        for (int i = 0; i < 8; i++) s += sh->sWarp[i];
        sh->sTot[0] = s;
    }
    __syncthreads();
    return sh->sTot[0];
}

__device__ __forceinline__ float wcoef(int m) {
    return (m < 12) ? cW12[m] : WINF;
}

__global__ __launch_bounds__(THREADS, 6)
void wass_kernel(const float* __restrict__ f,
                 const float* __restrict__ obs,
                 const float* __restrict__ t,
                 float* __restrict__ out) {
    __shared__ SharedBlk sh;

    const int row = blockIdx.x;
    const int tid = threadIdx.x;
    const int base = tid * CHUNK;
    const float dt = t[1] - t[0];

    // prefetch the f row into L2 while the obs phase runs
    {
        const char* fp = (const char*)(f + (size_t)row * NTd + base);
        asm volatile("prefetch.global.L2 [%0];" :: "l"(fp));
    }

    float y[CHUNK];

    // ================= obs phase: build padded CDF in shared =================
    {
        const float4* o4 = (const float4*)(obs + (size_t)row * NTd) + tid * 4;
        #pragma unroll
        for (int q = 0; q < 4; q++) {
            float4 v = o4[q];
            y[4 * q + 0] = fabsf(v.x); y[4 * q + 1] = fabsf(v.y);
            y[4 * q + 2] = fabsf(v.z); y[4 * q + 3] = fabsf(v.w);
        }
        sh.sFirst[tid] = y[0];
        __syncthreads();
        float ynext = (tid < THREADS - 1) ? sh.sFirst[tid + 1] : 0.0f;

        // local pair-sums; block total of these == sum(y) - 0.5*(y0 + ylast)
        float ls = 0.0f;
        #pragma unroll
        for (int k = 0; k < CHUNK - 1; ++k) ls += 0.5f * (y[k] + y[k + 1]);
        if (tid < THREADS - 1) ls += 0.5f * (y[CHUNK - 1] + ynext);
        float S;
        float cum = block_excl_scan_total(ls, &sh, &S);
        float inv = 1.0f / (dt * S);
        float scale = dt * inv;

        // vectorized CDF store: 4 x STS.128 per thread, conflict-free
        float4* dst = (float4*)&sh.sF[tid * 20];
        #pragma unroll
        for (int q = 0; q < 4; q++) {
            float4 st;
            st.x = cum * scale; cum += 0.5f * (y[4 * q + 0] + y[4 * q + 1]);
            st.y = cum * scale; cum += 0.5f * (y[4 * q + 1] + y[4 * q + 2]);
            st.z = cum * scale; cum += 0.5f * (y[4 * q + 2] + y[4 * q + 3]);
            st.w = cum * scale;
            float yn = (q < 3) ? y[4 * q + 4] : ynext;
            cum += 0.5f * (y[4 * q + 3] + yn);
            dst[q] = st;
        }
        __syncthreads();
    }

    // ---- inverse CDF at 100 quantiles (jnp.interp semantics) ----
    if (tid < NPd) {
        float p = (tid == NPd - 1) ? 1.0f : tid * HPc;
        float Flast = sh.sF[IDX2(NTd - 1)];
        float q;
        if (p > Flast) {
            q = (NTd - 1) * dt;                         // interp right clamp
        } else {
            int lo = 0, hi = NTd;                       // searchsorted right
            while (lo < hi) {
                int mid = (lo + hi) >> 1;
                if (sh.sF[IDX2(mid)] <= p) lo = mid + 1; else hi = mid;
            }
            int i = min(max(lo, 1), NTd - 1);
            float F0 = sh.sF[IDX2(i - 1)], F1 = sh.sF[IDX2(i)];
            q = (i - 1) * dt + (p - F0) * dt / (F1 - F0);
        }
        sh.sQ[tid] = q;
    }
    __syncthreads();

    // ---- natural cubic spline: fully parallel (truncated) Thomas ----
    if (tid < NPd - 2)
        sh.sR[tid] = 6.0f * (sh.sQ[tid + 2] - 2.0f * sh.sQ[tid + 1] + sh.sQ[tid]) / (HPc * HPc);
    __syncthreads();

    // forward sweep: thread i computes dp_i. Exact for i<16 (starts at m=0);
    // 16-term truncated otherwise (tail ~7e-10 rel).
    if (tid < NPd - 2) {
        int i = tid;
        int m0 = max(0, i - 15);
        float dp = 0.0f;
        #pragma unroll 1
        for (int m = m0; m <= i; ++m)
            dp = (sh.sR[m] - dp) * wcoef(m);
        sh.sDp[i] = dp;
    }
    __syncthreads();

    // backward sweep: thread i computes m_i -> sM[i+1].
    // Exact from the top for i>=82; truncated 16-term otherwise.
    if (tid < NPd - 3) {               // i in 0..96
        int i = tid;
        float mv; int mstart;
        if (i >= 82) { mv = sh.sDp[97]; mstart = 96; }
        else         { mv = 0.0f;       mstart = i + 15; }
        #pragma unroll 1
        for (int m = mstart; m >= i; --m)
            mv = sh.sDp[m] - wcoef(m) * mv;
        sh.sM[i + 1] = mv;
    } else if (tid == NPd - 3) {       // unreachable; kept for clarity
    }
    if (tid == 97) sh.sM[98] = sh.sDp[97];
    if (tid == 98) sh.sM[0] = 0.0f;
    if (tid == 99) sh.sM[99] = 0.0f;
    __syncthreads();

    // ---- pack per-segment coefficients ----
    if (tid < NPd - 1) {
        float Qj = sh.sQ[tid], Qj1 = sh.sQ[tid + 1];
        float Mj = sh.sM[tid], Mj1 = sh.sM[tid + 1];
        float a = Qj;
        float b = (Qj1 - Qj) / HPc - HPc * (2.0f * Mj + Mj1) / 6.0f;
        float c = Mj * 0.5f;
        float d = (Mj1 - Mj) / (6.0f * HPc);
        sh.coef[tid] = make_float4(a, b, c, d);
    }
    __syncthreads();

    // ================= f phase: renorm, CDF, spline eval, integrate =================
    float rowsum;
    {
        const float4* f4 = (const float4*)(f + (size_t)row * NTd) + tid * 4;
        #pragma unroll
        for (int q = 0; q < 4; q++) {
            float4 v = f4[q];
            y[4 * q + 0] = fabsf(v.x); y[4 * q + 1] = fabsf(v.y);
            y[4 * q + 2] = fabsf(v.z); y[4 * q + 3] = fabsf(v.w);
        }
        sh.sFirst[tid] = y[0];
        __syncthreads();
        float ynext = (tid < THREADS - 1) ? sh.sFirst[tid + 1] : 0.0f;

        float ls = 0.0f;
        #pragma unroll
        for (int k = 0; k < CHUNK - 1; ++k) ls += 0.5f * (y[k] + y[k + 1]);
        if (tid < THREADS - 1) ls += 0.5f * (y[CHUNK - 1] + ynext);
        float S;
        float cum = block_excl_scan_total(ls, &sh, &S);
        float inv = 1.0f / (dt * S);
        float scale = dt * inv;

        // eval loop with register-cached spline coefficient
        float acc = 0.0f;
        int pidx = -1;
        float4 cf = make_float4(0.f, 0.f, 0.f, 0.f);
        #pragma unroll
        for (int k = 0; k < CHUNK; ++k) {
            int j = base + k;
            float Fv = cum * scale;                 // >= 0 by construction
            float xi = fminf(Fv, 1.0f);
            int idx = min((int)(xi * 99.0f), 98);
            if (idx != pidx) { cf = sh.coef[idx]; pidx = idx; }
            float dxv = xi - idx * HPc;
            float off = cf.x + dxv * (cf.y + dxv * (cf.z + dxv * cf.w));
            float diff = j * dt - off;
            float wgt = (j == 0 || j == NTd - 1) ? 0.5f : 1.0f;
            acc += diff * diff * (y[k] * inv) * wgt;
            float yn = (k < CHUNK - 1) ? y[k + 1] : ynext;
            cum += 0.5f * (y[k] + yn);
        }
        rowsum = block_reduce_bcast(acc, &sh);
    }

    // ---- fused, deterministic final reduction (last block) ----
    if (tid == 0) {
        g_partials[row] = rowsum * dt;
        __threadfence();
        unsigned v = atomicAdd(&g_count, 1u);
        sh.isLast = (v == NROWS - 1) ? 1 : 0;
    }
    __syncthreads();
    if (sh.isLast) {
        int lane = tid & 31, w = tid >> 5;
        double s = 0.0;
        for (int i = tid; i < NROWS; i += THREADS)
            s += (double)__ldcg(&g_partials[i]);   // bypass L1: other SMs wrote these
        #pragma unroll
        for (int o = 16; o > 0; o >>= 1) s += __shfl_down_sync(0xffffffffu, s, o);
        __shared__ double dred[8];
        if (lane == 0) dred[w] = s;
        __syncthreads();
        if (tid == 0) {
            double x = 0.0;
            #pragma unroll
            for (int i = 0; i < 8; i++) x += dred[i];
            out[0] = (float)x;
            g_count = 0;               // reset for next graph replay
            __threadfence();
        }
    }
}

extern "C" void kernel_launch(void* const* d_in, const int* in_sizes, int n_in,
                              void* d_out, int out_size) {
    const float* f   = (const float*)d_in[0];
    const float* obs = (const float*)d_in[1];
    const float* t   = (const float*)d_in[2];
    wass_kernel<<<NROWS, THREADS>>>(f, obs, t, (float*)d_out);
}

// round 13
// speedup vs baseline: 1.1555x; 1.1555x over previous
#include <cuda_runtime.h>

#define NTd 4096
#define NROWS 2048
#define NPd 100
#define HPc (1.0f / 99.0f)
#define THREADS 256
#define CHUNK (NTd / THREADS)   // 16
#define WINF 0.26794919243112270f   // 2 - sqrt(3), Thomas coeff limit
// padded chunk layout: chunk c at sF[20*c .. 20*c+15]; 16B-aligned for STS.128
#define IDX2(j) (((j) >> 4) * 20 + ((j) & 15))

__device__ float g_partials[NROWS];
__device__ unsigned int g_count = 0;

struct SharedBlk {
    float sF[THREADS * 20];     // padded RAW cumulative sums (obs phase), 20KB
    float sFirst[THREADS];      // first element of each thread's chunk
    float sWarp[8];
    float sTot[1];
    float sQ[NPd];              // quantile function values
    float sR[NPd];              // Thomas rhs
    float sDp[NPd];             // Thomas forward-sweep values
    float sM[NPd];              // spline second derivatives M[0..99]
    float sW[24];               // exact elimination coeffs (first 20)
    float4 coef[NPd];           // packed {a,b,c,d} per segment (99 used)
    int isLast;
};

__device__ __forceinline__ float warp_incl_scan(float v) {
    int lane = threadIdx.x & 31;
    #pragma unroll
    for (int o = 1; o < 32; o <<= 1) {
        float tv = __shfl_up_sync(0xffffffffu, v, o);
        if (lane >= o) v += tv;
    }
    return v;
}

// exclusive scan; also returns the block-wide total (free: sWarp[7] after stage 2)
__device__ __forceinline__ float block_excl_scan_total(float v, SharedBlk* sh, float* total) {
    int tid = threadIdx.x, lane = tid & 31, w = tid >> 5;
    __syncthreads();                 // protect sWarp reuse across calls
    float incl = warp_incl_scan(v);
    if (lane == 31) sh->sWarp[w] = incl;
    __syncthreads();
    if (w == 0) {
        float x = (lane < 8) ? sh->sWarp[lane] : 0.0f;
        float xs = warp_incl_scan(x);
        if (lane < 8) sh->sWarp[lane] = xs;
    }
    __syncthreads();
    float off = (w > 0) ? sh->sWarp[w - 1] : 0.0f;
    *total = sh->sWarp[7];
    return off + incl - v;
}

__device__ __forceinline__ float block_reduce_bcast(float v, SharedBlk* sh) {
    int tid = threadIdx.x, lane = tid & 31, w = tid >> 5;
    __syncthreads();
    #pragma unroll
    for (int o = 16; o > 0; o >>= 1) v += __shfl_down_sync(0xffffffffu, v, o);
    if (lane == 0) sh->sWarp[w] = v;
    __syncthreads();
    if (tid == 0) {
        float s = 0.0f;
        #pragma unroll
        for (int i = 0; i < 8; i++) s += sh->sWarp[i];
        sh->sTot[0] = s;
    }
    __syncthreads();
    return sh->sTot[0];
}

__global__ __launch_bounds__(THREADS, 6)
void wass_kernel(const float* __restrict__ f,
                 const float* __restrict__ obs,
                 const float* __restrict__ t,
                 float* __restrict__ out) {
    __shared__ SharedBlk sh;

    const int row = blockIdx.x;
    const int tid = threadIdx.x;
    const int base = tid * CHUNK;
    const float dt = t[1] - t[0];

    // prefetch the f row into L2 while the obs phase runs
    {
        const char* fp = (const char*)(f + (size_t)row * NTd + base);
        asm volatile("prefetch.global.L2 [%0];" :: "l"(fp));
    }

    float y[CHUNK];
    float Sobs;   // block total of pair-sums == sum(y) - 0.5*(y0+ylast)

    // ================= obs phase: build RAW cumulative sums in shared =================
    {
        const float4* o4 = (const float4*)(obs + (size_t)row * NTd) + tid * 4;
        #pragma unroll
        for (int q = 0; q < 4; q++) {
            float4 v = o4[q];
            y[4 * q + 0] = fabsf(v.x); y[4 * q + 1] = fabsf(v.y);
            y[4 * q + 2] = fabsf(v.z); y[4 * q + 3] = fabsf(v.w);
        }
        sh.sFirst[tid] = y[0];
        __syncthreads();
        float ynext = (tid < THREADS - 1) ? sh.sFirst[tid + 1] : 0.0f;

        float ls = 0.0f;
        #pragma unroll
        for (int k = 0; k < CHUNK - 1; ++k) ls += 0.5f * (y[k] + y[k + 1]);
        if (tid < THREADS - 1) ls += 0.5f * (y[CHUNK - 1] + ynext);
        float cum = block_excl_scan_total(ls, &sh, &Sobs);

        // vectorized raw-cum store: 4 x STS.128 per thread, conflict-free.
        // F[j] = cum[j]/S; we search raw cum against p*S instead (saves 16 muls).
        float4* dst = (float4*)&sh.sF[tid * 20];
        #pragma unroll
        for (int q = 0; q < 4; q++) {
            float4 st;
            st.x = cum; cum += 0.5f * (y[4 * q + 0] + y[4 * q + 1]);
            st.y = cum; cum += 0.5f * (y[4 * q + 1] + y[4 * q + 2]);
            st.z = cum; cum += 0.5f * (y[4 * q + 2] + y[4 * q + 3]);
            st.w = cum;
            float yn = (q < 3) ? y[4 * q + 4] : ynext;
            cum += 0.5f * (y[4 * q + 3] + yn);
            dst[q] = st;
        }
        __syncthreads();
    }

    // ---- inverse CDF at 100 quantiles (jnp.interp semantics, raw units) ----
    if (tid < NPd) {
        float p = (tid == NPd - 1) ? 1.0f : tid * HPc;
        float pr = p * Sobs;                            // p in raw-cum units
        float Clast = sh.sF[IDX2(NTd - 1)];
        float q;
        if (pr > Clast) {
            q = (NTd - 1) * dt;                         // interp right clamp
        } else {
            int lo = 0, hi = NTd;                       // searchsorted right
            while (lo < hi) {
                int mid = (lo + hi) >> 1;
                if (sh.sF[IDX2(mid)] <= pr) lo = mid + 1; else hi = mid;
            }
            int i = min(max(lo, 1), NTd - 1);
            float C0 = sh.sF[IDX2(i - 1)], C1 = sh.sF[IDX2(i)];
            q = (i - 1) * dt + (pr - C0) * dt / (C1 - C0);
        }
        sh.sQ[tid] = q;
    }
    __syncthreads();

    // ---- natural cubic spline via parallelized (truncated) Thomas (R10 form) ----
    if (tid < NPd - 2)
        sh.sR[tid] = 6.0f * (sh.sQ[tid + 2] - 2.0f * sh.sQ[tid + 1] + sh.sQ[tid]) / (HPc * HPc);
    if (tid == 0) {
        float w = 0.25f;
        sh.sW[0] = w;
        for (int i = 1; i < 20; ++i) { w = 1.0f / (4.0f - w); sh.sW[i] = w; }
    }
    __syncthreads();

    // forward sweep: dp_i (98 unknowns, idx 0..97)
    if (tid >= 20 && tid < NPd - 2) {
        float s = sh.sR[tid - 15];
        #pragma unroll
        for (int q = 14; q >= 0; --q) s = sh.sR[tid - q] - WINF * s;
        sh.sDp[tid] = WINF * s;
    }
    if (tid == 0) {
        float dp = sh.sR[0] * 0.25f;
        sh.sDp[0] = dp;
        for (int i = 1; i < 20; ++i) { dp = (sh.sR[i] - dp) * sh.sW[i]; sh.sDp[i] = dp; }
    }
    __syncthreads();

    // backward sweep: m_i -> sM[i+1]; natural BCs sM[0]=sM[99]=0
    if (tid >= 8 && tid <= 77) {
        float s = sh.sDp[tid + 15];
        #pragma unroll
        for (int q = 14; q >= 0; --q) s = sh.sDp[tid + q] - WINF * s;
        sh.sM[tid + 1] = s;
    }
    if (tid == 0) {
        float mv = sh.sDp[97];
        sh.sM[98] = mv;
        for (int i = 96; i >= 78; --i) { mv = sh.sDp[i] - WINF * mv; sh.sM[i + 1] = mv; }
        sh.sM[0] = 0.0f;
        sh.sM[99] = 0.0f;
    }
    __syncthreads();
    if (tid == 0) {
        float mv = sh.sM[9];   // m_8
        for (int i = 7; i >= 0; --i) { mv = sh.sDp[i] - sh.sW[i] * mv; sh.sM[i + 1] = mv; }
    }
    __syncthreads();

    // ---- pack per-segment coefficients ----
    if (tid < NPd - 1) {
        float Qj = sh.sQ[tid], Qj1 = sh.sQ[tid + 1];
        float Mj = sh.sM[tid], Mj1 = sh.sM[tid + 1];
        float a = Qj;
        float b = (Qj1 - Qj) / HPc - HPc * (2.0f * Mj + Mj1) / 6.0f;
        float c = Mj * 0.5f;
        float d = (Mj1 - Mj) / (6.0f * HPc);
        sh.coef[tid] = make_float4(a, b, c, d);
    }
    __syncthreads();

    // ================= f phase: renorm, CDF, spline eval, integrate =================
    float rowsum, invf;
    {
        const float4* f4 = (const float4*)(f + (size_t)row * NTd) + tid * 4;
        #pragma unroll
        for (int q = 0; q < 4; q++) {
            float4 v = f4[q];
            y[4 * q + 0] = fabsf(v.x); y[4 * q + 1] = fabsf(v.y);
            y[4 * q + 2] = fabsf(v.z); y[4 * q + 3] = fabsf(v.w);
        }
        sh.sFirst[tid] = y[0];
        __syncthreads();
        float ynext = (tid < THREADS - 1) ? sh.sFirst[tid + 1] : 0.0f;

        float ls = 0.0f;
        #pragma unroll
        for (int k = 0; k < CHUNK - 1; ++k) ls += 0.5f * (y[k] + y[k + 1]);
        if (tid < THREADS - 1) ls += 0.5f * (y[CHUNK - 1] + ynext);
        float S;
        float cum = block_excl_scan_total(ls, &sh, &S);
        invf = 1.0f / (dt * S);
        float scale = dt * invf;

        // eval loop: register-cached coef; inv factored out; endpoint weights
        // applied as post-corrections (branchless inner loop).
        float acc = 0.0f, term0 = 0.0f, termL = 0.0f;
        int pidx = -1;
        float4 cf = make_float4(0.f, 0.f, 0.f, 0.f);
        #pragma unroll
        for (int k = 0; k < CHUNK; ++k) {
            int j = base + k;
            float Fv = cum * scale;                 // >= 0 by construction
            float xi = fminf(Fv, 1.0f);
            int idx = min((int)(xi * 99.0f), 98);
            if (idx != pidx) { cf = sh.coef[idx]; pidx = idx; }
            float dxv = xi - idx * HPc;
            float off = cf.x + dxv * (cf.y + dxv * (cf.z + dxv * cf.w));
            float diff = j * dt - off;
            float term = diff * diff * y[k];
            if (k == 0) term0 = term;               // compile-time condition
            if (k == CHUNK - 1) termL = term;
            acc += term;
            float yn = (k < CHUNK - 1) ? y[k + 1] : ynext;
            cum += 0.5f * (y[k] + yn);
        }
        if (tid == 0) acc -= 0.5f * term0;              // trapezoid end weights
        if (tid == THREADS - 1) acc -= 0.5f * termL;
        rowsum = block_reduce_bcast(acc, &sh);
    }

    // ---- fused, deterministic final reduction (last block) ----
    if (tid == 0) {
        g_partials[row] = rowsum * dt * invf;
        __threadfence();
        unsigned v = atomicAdd(&g_count, 1u);
        sh.isLast = (v == NROWS - 1) ? 1 : 0;
    }
    __syncthreads();
    if (sh.isLast) {
        int lane = tid & 31, w = tid >> 5;
        double s = 0.0;
        for (int i = tid; i < NROWS; i += THREADS)
            s += (double)__ldcg(&g_partials[i]);   // bypass L1: other SMs wrote these
        #pragma unroll
        for (int o = 16; o > 0; o >>= 1) s += __shfl_down_sync(0xffffffffu, s, o);
        __shared__ double dred[8];
        if (lane == 0) dred[w] = s;
        __syncthreads();
        if (tid == 0) {
            double x = 0.0;
            #pragma unroll
            for (int i = 0; i < 8; i++) x += dred[i];
            out[0] = (float)x;
            g_count = 0;               // reset for next graph replay
            __threadfence();
        }
    }
}

extern "C" void kernel_launch(void* const* d_in, const int* in_sizes, int n_in,
                              void* d_out, int out_size) {
    const float* f   = (const float*)d_in[0];
    const float* obs = (const float*)d_in[1];
    const float* t   = (const float*)d_in[2];
    wass_kernel<<<NROWS, THREADS>>>(f, obs, t, (float*)d_out);
}

// round 15
// speedup vs baseline: 1.1662x; 1.0092x over previous
#include <cuda_runtime.h>

#define NTd 4096
#define NROWS 2048
#define NPd 100
#define HPc (1.0f / 99.0f)
#define THREADS 256
#define CHUNK (NTd / THREADS)   // 16
#define WINF 0.26794919243112270f   // 2 - sqrt(3), Thomas coeff limit
// padded chunk layout: chunk c at sF[20*c .. 20*c+15]; 16B-aligned for STS.128
#define IDX2(j) (((j) >> 4) * 20 + ((j) & 15))

__device__ float g_partials[NROWS];
__device__ unsigned int g_count = 0;

// exact elimination coeffs w_m = 1/(4 - w_{m-1}); == WINF in fp32 for m >= 12
__constant__ float cW12[12] = {
    0.25f,
    0.26666666666666666f,
    0.26785714285714285f,
    0.26794258373205740f,
    0.26794871794871794f,
    0.26794915836482310f,
    0.26794918998527240f,
    0.26794919225552000f,
    0.26794919241862690f,
    0.26794919243035000f,
    0.26794919243117080f,
    0.26794919243112270f
};

__device__ __forceinline__ float wcoef(int m) {
    return (m < 12) ? cW12[m] : WINF;
}

struct SharedBlk {
    float sF[THREADS * 20];     // padded RAW cumulative sums (obs phase), 20KB
    float sFirst[THREADS];      // first element of each thread's chunk
    float sWarp[8];
    float sTot[1];
    float sQ[NPd];              // quantile function values
    float sR[NPd];              // Thomas rhs
    float sDp[NPd];             // Thomas forward-sweep values
    float sM[NPd];              // spline second derivatives M[0..99]
    float4 coef[NPd];           // packed {a,b,c,d} per segment (99 used)
    int isLast;
};

__device__ __forceinline__ float warp_incl_scan(float v) {
    int lane = threadIdx.x & 31;
    #pragma unroll
    for (int o = 1; o < 32; o <<= 1) {
        float tv = __shfl_up_sync(0xffffffffu, v, o);
        if (lane >= o) v += tv;
    }
    return v;
}

// exclusive scan; also returns the block-wide total (free: sWarp[7] after stage 2)
__device__ __forceinline__ float block_excl_scan_total(float v, SharedBlk* sh, float* total) {
    int tid = threadIdx.x, lane = tid & 31, w = tid >> 5;
    __syncthreads();                 // protect sWarp reuse across calls
    float incl = warp_incl_scan(v);
    if (lane == 31) sh->sWarp[w] = incl;
    __syncthreads();
    if (w == 0) {
        float x = (lane < 8) ? sh->sWarp[lane] : 0.0f;
        float xs = warp_incl_scan(x);
        if (lane < 8) sh->sWarp[lane] = xs;
    }
    __syncthreads();
    float off = (w > 0) ? sh->sWarp[w - 1] : 0.0f;
    *total = sh->sWarp[7];
    return off + incl - v;
}

__device__ __forceinline__ float block_reduce_bcast(float v, SharedBlk* sh) {
    int tid = threadIdx.x, lane = tid & 31, w = tid >> 5;
    __syncthreads();
    #pragma unroll
    for (int o = 16; o > 0; o >>= 1) v += __shfl_down_sync(0xffffffffu, v, o);
    if (lane == 0) sh->sWarp[w] = v;
    __syncthreads();
    if (tid == 0) {
        float s = 0.0f;
        #pragma unroll
        for (int i = 0; i < 8; i++) s += sh->sWarp[i];
        sh->sTot[0] = s;
    }
    __syncthreads();
    return sh->sTot[0];
}

__global__ __launch_bounds__(THREADS, 6)
void wass_kernel(const float* __restrict__ f,
                 const float* __restrict__ obs,
                 const float* __restrict__ t,
                 float* __restrict__ out) {
    __shared__ SharedBlk sh;

    const int row = blockIdx.x;
    const int tid = threadIdx.x;
    const int base = tid * CHUNK;
    const float dt = t[1] - t[0];

    // prefetch the f row into L2 while the obs phase runs
    {
        const char* fp = (const char*)(f + (size_t)row * NTd + base);
        asm volatile("prefetch.global.L2 [%0];" :: "l"(fp));
    }

    float y[CHUNK];
    float Sobs;   // block total of pair-sums == sum(y) - 0.5*(y0+ylast)

    // ================= obs phase: build RAW cumulative sums in shared =================
    {
        const float4* o4 = (const float4*)(obs + (size_t)row * NTd) + tid * 4;
        #pragma unroll
        for (int q = 0; q < 4; q++) {
            float4 v = o4[q];
            y[4 * q + 0] = fabsf(v.x); y[4 * q + 1] = fabsf(v.y);
            y[4 * q + 2] = fabsf(v.z); y[4 * q + 3] = fabsf(v.w);
        }
        sh.sFirst[tid] = y[0];
        __syncthreads();
        float ynext = (tid < THREADS - 1) ? sh.sFirst[tid + 1] : 0.0f;

        float ls = 0.0f;
        #pragma unroll
        for (int k = 0; k < CHUNK - 1; ++k) ls += 0.5f * (y[k] + y[k + 1]);
        if (tid < THREADS - 1) ls += 0.5f * (y[CHUNK - 1] + ynext);
        float cum = block_excl_scan_total(ls, &sh, &Sobs);

        // vectorized raw-cum store: 4 x STS.128 per thread, conflict-free
        float4* dst = (float4*)&sh.sF[tid * 20];
        #pragma unroll
        for (int q = 0; q < 4; q++) {
            float4 st;
            st.x = cum; cum += 0.5f * (y[4 * q + 0] + y[4 * q + 1]);
            st.y = cum; cum += 0.5f * (y[4 * q + 1] + y[4 * q + 2]);
            st.z = cum; cum += 0.5f * (y[4 * q + 2] + y[4 * q + 3]);
            st.w = cum;
            float yn = (q < 3) ? y[4 * q + 4] : ynext;
            cum += 0.5f * (y[4 * q + 3] + yn);
            dst[q] = st;
        }
        __syncthreads();
    }

    // ---- inverse CDF at 100 quantiles (jnp.interp semantics, raw units) ----
    if (tid < NPd) {
        float p = (tid == NPd - 1) ? 1.0f : tid * HPc;
        float pr = p * Sobs;                            // p in raw-cum units
        float Clast = sh.sF[IDX2(NTd - 1)];
        float q;
        if (pr > Clast) {
            q = (NTd - 1) * dt;                         // interp right clamp
        } else {
            int lo = 0, hi = NTd;                       // searchsorted right
            while (lo < hi) {
                int mid = (lo + hi) >> 1;
                if (sh.sF[IDX2(mid)] <= pr) lo = mid + 1; else hi = mid;
            }
            int i = min(max(lo, 1), NTd - 1);
            float C0 = sh.sF[IDX2(i - 1)], C1 = sh.sF[IDX2(i)];
            q = (i - 1) * dt + (pr - C0) * dt / (C1 - C0);
        }
        sh.sQ[tid] = q;
    }
    __syncthreads();

    // ---- natural cubic spline via parallelized (truncated) Thomas ----
    if (tid < NPd - 2)
        sh.sR[tid] = 6.0f * (sh.sQ[tid + 2] - 2.0f * sh.sQ[tid + 1] + sh.sQ[tid]) / (HPc * HPc);
    __syncthreads();

    // forward sweep: dp_i (98 unknowns, idx 0..97)
    if (tid >= 20 && tid < NPd - 2) {
        float s = sh.sR[tid - 15];
        #pragma unroll
        for (int q = 14; q >= 0; --q) s = sh.sR[tid - q] - WINF * s;
        sh.sDp[tid] = WINF * s;
    }
    if (tid == 0) {
        float dp = sh.sR[0] * 0.25f;
        sh.sDp[0] = dp;
        #pragma unroll
        for (int i = 1; i < 20; ++i) { dp = (sh.sR[i] - dp) * wcoef(i); sh.sDp[i] = dp; }
    }
    __syncthreads();

    // backward sweep, single phase:
    //   tid 8..77   : truncated mid values -> sM[9..78]
    //   tid 0       : exact top stub from sDp[97] -> sM[98..79]
    //   tid 128     : recompute truncated m_8 (same recursion as tid 8),
    //                 then exact-coefficient walk down -> sM[8..1]
    if (tid >= 8 && tid <= 77) {
        float s = sh.sDp[tid + 15];
        #pragma unroll
        for (int q = 14; q >= 0; --q) s = sh.sDp[tid + q] - WINF * s;
        sh.sM[tid + 1] = s;
    } else if (tid == 0) {
        float mv = sh.sDp[97];
        sh.sM[98] = mv;
        #pragma unroll
        for (int i = 96; i >= 78; --i) { mv = sh.sDp[i] - WINF * mv; sh.sM[i + 1] = mv; }
    } else if (tid == 128) {
        float s = sh.sDp[8 + 15];                  // truncated m_8, identical to tid 8's
        #pragma unroll
        for (int q = 14; q >= 0; --q) s = sh.sDp[8 + q] - WINF * s;
        float mv = s;
        #pragma unroll
        for (int i = 7; i >= 0; --i) { mv = sh.sDp[i] - wcoef(i) * mv; sh.sM[i + 1] = mv; }
    } else if (tid == 129) {
        sh.sM[0] = 0.0f;
    } else if (tid == 130) {
        sh.sM[99] = 0.0f;
    }
    __syncthreads();

    // ---- pack per-segment coefficients ----
    if (tid < NPd - 1) {
        float Qj = sh.sQ[tid], Qj1 = sh.sQ[tid + 1];
        float Mj = sh.sM[tid], Mj1 = sh.sM[tid + 1];
        float a = Qj;
        float b = (Qj1 - Qj) / HPc - HPc * (2.0f * Mj + Mj1) / 6.0f;
        float c = Mj * 0.5f;
        float d = (Mj1 - Mj) / (6.0f * HPc);
        sh.coef[tid] = make_float4(a, b, c, d);
    }
    __syncthreads();

    // ================= f phase: renorm, CDF, spline eval, integrate =================
    float rowsum, invf;
    {
        const float4* f4 = (const float4*)(f + (size_t)row * NTd) + tid * 4;
        #pragma unroll
        for (int q = 0; q < 4; q++) {
            float4 v = f4[q];
            y[4 * q + 0] = fabsf(v.x); y[4 * q + 1] = fabsf(v.y);
            y[4 * q + 2] = fabsf(v.z); y[4 * q + 3] = fabsf(v.w);
        }
        sh.sFirst[tid] = y[0];
        __syncthreads();
        float ynext = (tid < THREADS - 1) ? sh.sFirst[tid + 1] : 0.0f;

        float ls = 0.0f;
        #pragma unroll
        for (int k = 0; k < CHUNK - 1; ++k) ls += 0.5f * (y[k] + y[k + 1]);
        if (tid < THREADS - 1) ls += 0.5f * (y[CHUNK - 1] + ynext);
        float S;
        float cum = block_excl_scan_total(ls, &sh, &S);
        invf = 1.0f / (dt * S);
        float scale = dt * invf;

        // eval loop: register-cached coef; inv factored out; endpoint weights
        // as post-corrections; incremental time coordinate tj.
        float acc = 0.0f, term0 = 0.0f, termL = 0.0f;
        float tj = base * dt;
        int pidx = -1;
        float4 cf = make_float4(0.f, 0.f, 0.f, 0.f);
        #pragma unroll
        for (int k = 0; k < CHUNK; ++k) {
            float Fv = cum * scale;                 // >= 0 by construction
            float xi = fminf(Fv, 1.0f);
            int idx = min((int)(xi * 99.0f), 98);
            if (idx != pidx) { cf = sh.coef[idx]; pidx = idx; }
            float dxv = xi - idx * HPc;
            float off = cf.x + dxv * (cf.y + dxv * (cf.z + dxv * cf.w));
            float diff = tj - off;
            float term = diff * diff * y[k];
            if (k == 0) term0 = term;               // compile-time condition
            if (k == CHUNK - 1) termL = term;
            acc += term;
            float yn = (k < CHUNK - 1) ? y[k + 1] : ynext;
            cum += 0.5f * (y[k] + yn);
            tj += dt;
        }
        if (tid == 0) acc -= 0.5f * term0;              // trapezoid end weights
        if (tid == THREADS - 1) acc -= 0.5f * termL;
        rowsum = block_reduce_bcast(acc, &sh);
    }

    // ---- fused, deterministic final reduction (last block) ----
    if (tid == 0) {
        g_partials[row] = rowsum * dt * invf;
        __threadfence();
        unsigned v = atomicAdd(&g_count, 1u);
        sh.isLast = (v == NROWS - 1) ? 1 : 0;
    }
    __syncthreads();
    if (sh.isLast) {
        int lane = tid & 31, w = tid >> 5;
        double s = 0.0;
        for (int i = tid; i < NROWS; i += THREADS)
            s += (double)__ldcg(&g_partials[i]);   // bypass L1: other SMs wrote these
        #pragma unroll
        for (int o = 16; o > 0; o >>= 1) s += __shfl_down_sync(0xffffffffu, s, o);
        __shared__ double dred[8];
        if (lane == 0) dred[w] = s;
        __syncthreads();
        if (tid == 0) {
            double x = 0.0;
            #pragma unroll
            for (int i = 0; i < 8; i++) x += dred[i];
            out[0] = (float)x;
            g_count = 0;               // reset for next graph replay
            __threadfence();
        }
    }
}

extern "C" void kernel_launch(void* const* d_in, const int* in_sizes, int n_in,
                              void* d_out, int out_size) {
    const float* f   = (const float*)d_in[0];
    const float* obs = (const float*)d_in[1];
    const float* t   = (const float*)d_in[2];
    wass_kernel<<<NROWS, THREADS>>>(f, obs, t, (float*)d_out);
}